// round 7
// baseline (speedup 1.0000x reference)
#include <cuda_runtime.h>

#define C_DIM   256
#define MAXN    100000
#define EPS_LN  1e-5f

// ---------------------------------------------------------------------------
// Scratch (device globals; no allocation allowed in kernel_launch)
// ---------------------------------------------------------------------------
__device__ float g_cur_u[MAXN * C_DIM];
__device__ float g_cur_i[MAXN * C_DIM];
__device__ float g_H    [MAXN * C_DIM];
__device__ float g_P    [MAXN * C_DIM];
__device__ float g_agg  [MAXN * C_DIM];
__device__ float g_new_u[MAXN * C_DIM];
__device__ float g_new_i[MAXN * C_DIM];
__device__ float g_cnt  [MAXN];

// ---------------------------------------------------------------------------
// GEMM: C[M,N] = op(A[M,K] @ B[K,N] (+bias) (+Cold)) with optional relu.
// 128x128 block, BK=16, 256 threads, 8x8 register micro-tile.
// ---------------------------------------------------------------------------
template<bool RELU, bool ACCUM, bool BIAS>
__global__ __launch_bounds__(256, 2)
void gemm128_kernel(const float* __restrict__ A, const float* __restrict__ B,
                    const float* __restrict__ bias, float* __restrict__ Cout,
                    int M, int K, int N)
{
    __shared__ float As[16][128];   // stored transposed: As[k][m]
    __shared__ float Bs[16][128];   // Bs[k][n]

    const int tid = threadIdx.x;
    const int tx  = tid & 15;       // column group (8 cols each)
    const int ty  = tid >> 4;       // row group (8 rows each)
    const int bx  = blockIdx.x * 128;
    const int by  = blockIdx.y * 128;

    float acc[8][8];
#pragma unroll
    for (int i = 0; i < 8; i++)
#pragma unroll
        for (int j = 0; j < 8; j++) acc[i][j] = 0.f;

    for (int k0 = 0; k0 < K; k0 += 16) {
        // Load A tile [128 x 16] -> transposed smem
#pragma unroll
        for (int i = 0; i < 2; i++) {
            int idx = tid + i * 256;        // 0..511 float4 slots
            int r   = idx >> 2;             // 0..127 row in tile
            int c4  = (idx & 3) << 2;       // 0,4,8,12
            int grow = by + r;
            float4 v = make_float4(0.f, 0.f, 0.f, 0.f);
            if (grow < M)
                v = *(const float4*)(A + (size_t)grow * K + k0 + c4);
            As[c4 + 0][r] = v.x;
            As[c4 + 1][r] = v.y;
            As[c4 + 2][r] = v.z;
            As[c4 + 3][r] = v.w;
        }
        // Load B tile [16 x 128]
#pragma unroll
        for (int i = 0; i < 2; i++) {
            int idx = tid + i * 256;
            int r   = idx >> 5;             // 0..15
            int cc  = (idx & 31) << 2;      // 0..124
            *(float4*)(&Bs[r][cc]) =
                *(const float4*)(B + (size_t)(k0 + r) * N + bx + cc);
        }
        __syncthreads();

#pragma unroll
        for (int kk = 0; kk < 16; kk++) {
            float4 a0 = *(const float4*)(&As[kk][ty * 8]);
            float4 a1 = *(const float4*)(&As[kk][ty * 8 + 4]);
            float4 b0 = *(const float4*)(&Bs[kk][tx * 8]);
            float4 b1 = *(const float4*)(&Bs[kk][tx * 8 + 4]);
            float a[8] = {a0.x, a0.y, a0.z, a0.w, a1.x, a1.y, a1.z, a1.w};
            float b[8] = {b0.x, b0.y, b0.z, b0.w, b1.x, b1.y, b1.z, b1.w};
#pragma unroll
            for (int i = 0; i < 8; i++)
#pragma unroll
                for (int j = 0; j < 8; j++)
                    acc[i][j] = fmaf(a[i], b[j], acc[i][j]);
        }
        __syncthreads();
    }

    // Epilogue
    float4 bv0 = make_float4(0.f, 0.f, 0.f, 0.f);
    float4 bv1 = make_float4(0.f, 0.f, 0.f, 0.f);
    if (BIAS) {
        bv0 = *(const float4*)(bias + bx + tx * 8);
        bv1 = *(const float4*)(bias + bx + tx * 8 + 4);
    }
#pragma unroll
    for (int i = 0; i < 8; i++) {
        int row = by + ty * 8 + i;
        if (row >= M) break;
        float* crow = Cout + (size_t)row * N + bx + tx * 8;
#pragma unroll
        for (int jj = 0; jj < 2; jj++) {
            float4 v = make_float4(acc[i][jj * 4 + 0], acc[i][jj * 4 + 1],
                                   acc[i][jj * 4 + 2], acc[i][jj * 4 + 3]);
            if (BIAS) {
                float4 bb = jj ? bv1 : bv0;
                v.x += bb.x; v.y += bb.y; v.z += bb.z; v.w += bb.w;
            }
            if (ACCUM) {
                float4 ov = *(const float4*)(crow + jj * 4);
                v.x += ov.x; v.y += ov.y; v.z += ov.z; v.w += ov.w;
            }
            if (RELU) {
                v.x = fmaxf(v.x, 0.f); v.y = fmaxf(v.y, 0.f);
                v.z = fmaxf(v.z, 0.f); v.w = fmaxf(v.w, 0.f);
            }
            *(float4*)(crow + jj * 4) = v;
        }
    }
}

// ---------------------------------------------------------------------------
// Warp reduce
// ---------------------------------------------------------------------------
__device__ __forceinline__ float warp_sum(float v)
{
#pragma unroll
    for (int o = 16; o > 0; o >>= 1)
        v += __shfl_xor_sync(0xffffffffu, v, o);
    return v;
}

// ---------------------------------------------------------------------------
// Edge stage: one warp per edge.
//   msg = LN(x_src[src] - P[dst]) * g + b
//   agg[dst] += msg (vector red), cnt[dst] += 1
// ---------------------------------------------------------------------------
__global__ void edge_msg_kernel(const float* __restrict__ xsrc,
                                const float* __restrict__ Pn,
                                const int*   __restrict__ ei,
                                const float* __restrict__ gg,
                                const float* __restrict__ bb,
                                float* __restrict__ agg,
                                float* __restrict__ cnt,
                                int nE)
{
    int w    = (blockIdx.x * blockDim.x + threadIdx.x) >> 5;
    int lane = threadIdx.x & 31;
    if (w >= nE) return;

    int s = __ldg(ei + w);
    int d = __ldg(ei + nE + w);
    int c0 = lane << 3;

    const float4* xs = (const float4*)(xsrc + (size_t)s * C_DIM + c0);
    const float4* pp = (const float4*)(Pn   + (size_t)d * C_DIM + c0);
    float4 a0 = xs[0], a1 = xs[1];
    float4 p0 = pp[0], p1 = pp[1];
    float r[8] = {a0.x - p0.x, a0.y - p0.y, a0.z - p0.z, a0.w - p0.w,
                  a1.x - p1.x, a1.y - p1.y, a1.z - p1.z, a1.w - p1.w};

    float s1 = 0.f;
#pragma unroll
    for (int i = 0; i < 8; i++) s1 += r[i];
    s1 = warp_sum(s1);
    float mean = s1 * (1.f / 256.f);

    float s2 = 0.f;
#pragma unroll
    for (int i = 0; i < 8; i++) { float t = r[i] - mean; s2 += t * t; }
    s2 = warp_sum(s2);
    float inv = rsqrtf(s2 * (1.f / 256.f) + EPS_LN);

    float4 g0 = *(const float4*)(gg + c0);
    float4 g1 = *(const float4*)(gg + c0 + 4);
    float4 e0 = *(const float4*)(bb + c0);
    float4 e1 = *(const float4*)(bb + c0 + 4);

    float m[8];
    m[0] = (r[0] - mean) * inv * g0.x + e0.x;
    m[1] = (r[1] - mean) * inv * g0.y + e0.y;
    m[2] = (r[2] - mean) * inv * g0.z + e0.z;
    m[3] = (r[3] - mean) * inv * g0.w + e0.w;
    m[4] = (r[4] - mean) * inv * g1.x + e1.x;
    m[5] = (r[5] - mean) * inv * g1.y + e1.y;
    m[6] = (r[6] - mean) * inv * g1.z + e1.z;
    m[7] = (r[7] - mean) * inv * g1.w + e1.w;

    float* dstp = agg + (size_t)d * C_DIM + c0;
    asm volatile("red.global.add.v4.f32 [%0], {%1,%2,%3,%4};"
                 :: "l"(dstp), "f"(m[0]), "f"(m[1]), "f"(m[2]), "f"(m[3])
                 : "memory");
    asm volatile("red.global.add.v4.f32 [%0], {%1,%2,%3,%4};"
                 :: "l"(dstp + 4), "f"(m[4]), "f"(m[5]), "f"(m[6]), "f"(m[7])
                 : "memory");
    if (lane == 0) atomicAdd(cnt + d, 1.0f);
}

// ---------------------------------------------------------------------------
// agg[i] /= max(cnt[i], 1)
// ---------------------------------------------------------------------------
__global__ void norm_agg_kernel(float* __restrict__ agg,
                                const float* __restrict__ cnt, int n)
{
    int idx = blockIdx.x * blockDim.x + threadIdx.x;   // one float4 each
    int total = n * (C_DIM / 4);
    if (idx >= total) return;
    int row = idx / (C_DIM / 4);
    float inv = 1.f / fmaxf(__ldg(cnt + row), 1.f);
    float4* p = ((float4*)agg) + idx;
    float4 v = *p;
    v.x *= inv; v.y *= inv; v.z *= inv; v.w *= inv;
    *p = v;
}

// ---------------------------------------------------------------------------
// out = relu(LN(X) * g + b), one warp per row
// ---------------------------------------------------------------------------
__global__ void node_ln_relu_kernel(const float* __restrict__ X,
                                    const float* __restrict__ gg,
                                    const float* __restrict__ bb,
                                    float* __restrict__ out, int M)
{
    int w    = (blockIdx.x * blockDim.x + threadIdx.x) >> 5;
    int lane = threadIdx.x & 31;
    if (w >= M) return;
    int c0 = lane << 3;

    const float4* xp = (const float4*)(X + (size_t)w * C_DIM + c0);
    float4 a0 = xp[0], a1 = xp[1];
    float r[8] = {a0.x, a0.y, a0.z, a0.w, a1.x, a1.y, a1.z, a1.w};

    float s1 = 0.f;
#pragma unroll
    for (int i = 0; i < 8; i++) s1 += r[i];
    s1 = warp_sum(s1);
    float mean = s1 * (1.f / 256.f);

    float s2 = 0.f;
#pragma unroll
    for (int i = 0; i < 8; i++) { float t = r[i] - mean; s2 += t * t; }
    s2 = warp_sum(s2);
    float inv = rsqrtf(s2 * (1.f / 256.f) + EPS_LN);

    float4 g0 = *(const float4*)(gg + c0);
    float4 g1 = *(const float4*)(gg + c0 + 4);
    float4 e0 = *(const float4*)(bb + c0);
    float4 e1 = *(const float4*)(bb + c0 + 4);

    float4 o0, o1;
    o0.x = fmaxf((r[0] - mean) * inv * g0.x + e0.x, 0.f);
    o0.y = fmaxf((r[1] - mean) * inv * g0.y + e0.y, 0.f);
    o0.z = fmaxf((r[2] - mean) * inv * g0.z + e0.z, 0.f);
    o0.w = fmaxf((r[3] - mean) * inv * g0.w + e0.w, 0.f);
    o1.x = fmaxf((r[4] - mean) * inv * g1.x + e1.x, 0.f);
    o1.y = fmaxf((r[5] - mean) * inv * g1.y + e1.y, 0.f);
    o1.z = fmaxf((r[6] - mean) * inv * g1.z + e1.z, 0.f);
    o1.w = fmaxf((r[7] - mean) * inv * g1.w + e1.w, 0.f);

    float4* op = (float4*)(out + (size_t)w * C_DIM + c0);
    op[0] = o0;
    op[1] = o1;
}

// ---------------------------------------------------------------------------
// Host-side conv driver (all launches on default stream, graph-capturable)
// ---------------------------------------------------------------------------
static void launch_conv(const float* xsrc, const float* xdst, int n_dst,
                        const int* ei, int nE,
                        const float* w1, const float* b1,
                        const float* w2, const float* b2,
                        const float* mg, const float* mb,
                        const float* lw, const float* lb,
                        float* Hbuf, float* Pbuf, float* aggbuf, float* cntbuf,
                        float* outbuf)
{
    dim3 blk(256);
    dim3 grd(C_DIM / 128, (n_dst + 127) / 128);

    // P = relu(xdst @ W1 + b1) @ W2 + b2   (per destination node, not per edge)
    gemm128_kernel<true,  false, true ><<<grd, blk>>>(xdst, w1, b1, Hbuf, n_dst, C_DIM, C_DIM);
    gemm128_kernel<false, false, true ><<<grd, blk>>>(Hbuf, w2, b2, Pbuf, n_dst, C_DIM, C_DIM);

    cudaMemsetAsync(aggbuf, 0, (size_t)n_dst * C_DIM * sizeof(float));
    cudaMemsetAsync(cntbuf, 0, (size_t)n_dst * sizeof(float));

    int eb = (nE * 32 + 255) / 256;
    edge_msg_kernel<<<eb, 256>>>(xsrc, Pbuf, ei, mg, mb, aggbuf, cntbuf, nE);

    int nb = (n_dst * (C_DIM / 4) + 255) / 256;
    norm_agg_kernel<<<nb, 256>>>(aggbuf, cntbuf, n_dst);

    // out = xdst @ Wx + aggn @ Wa + lb   (split of concat GEMM)
    gemm128_kernel<false, false, true ><<<grd, blk>>>(xdst,   lw,                 lb,      outbuf, n_dst, C_DIM, C_DIM);
    gemm128_kernel<false, true,  false><<<grd, blk>>>(aggbuf, lw + C_DIM * C_DIM, nullptr, outbuf, n_dst, C_DIM, C_DIM);
}

extern "C" void kernel_launch(void* const* d_in, const int* in_sizes, int n_in,
                              void* d_out, int out_size)
{
    const float* x_user = (const float*)d_in[0];
    const float* x_item = (const float*)d_in[1];
    const float* pw1    = (const float*)d_in[2];
    const float* pb1    = (const float*)d_in[3];
    const float* pw2    = (const float*)d_in[4];
    const float* pb2    = (const float*)d_in[5];
    const float* msg_g  = (const float*)d_in[6];
    const float* msg_b  = (const float*)d_in[7];
    const float* lin_w  = (const float*)d_in[8];
    const float* lin_b  = (const float*)d_in[9];
    const float* node_g = (const float*)d_in[10];
    const float* node_b = (const float*)d_in[11];
    const int*   ei_ui  = (const int*)d_in[12];
    const int*   ei_iu  = (const int*)d_in[13];

    const int NUn = in_sizes[0] / C_DIM;
    const int NIn = in_sizes[1] / C_DIM;
    const int nE0 = in_sizes[12] / 2;   // user->item edges
    const int nE1 = in_sizes[13] / 2;   // item->user edges
    const int Lm  = 2;

    float *cur_u, *cur_i, *Hb, *Pb, *aggb, *cntb, *new_u, *new_i;
    cudaGetSymbolAddress((void**)&cur_u, g_cur_u);
    cudaGetSymbolAddress((void**)&cur_i, g_cur_i);
    cudaGetSymbolAddress((void**)&Hb,    g_H);
    cudaGetSymbolAddress((void**)&Pb,    g_P);
    cudaGetSymbolAddress((void**)&aggb,  g_agg);
    cudaGetSymbolAddress((void**)&cntb,  g_cnt);
    cudaGetSymbolAddress((void**)&new_u, g_new_u);
    cudaGetSymbolAddress((void**)&new_i, g_new_i);

    cudaMemcpyAsync(cur_u, x_user, (size_t)NUn * C_DIM * sizeof(float),
                    cudaMemcpyDeviceToDevice);
    cudaMemcpyAsync(cur_i, x_item, (size_t)NIn * C_DIM * sizeof(float),
                    cudaMemcpyDeviceToDevice);

    float* out_f = (float*)d_out;

    for (int l = 0; l < Lm; l++) {
        // edge type 0: user -> item (dst = item), params [l,0]
        {
            int t = l * 2 + 0;
            launch_conv(cur_u, cur_i, NIn, ei_ui, nE0,
                        pw1 + (size_t)t * C_DIM * C_DIM, pb1 + (size_t)t * C_DIM,
                        pw2 + (size_t)t * C_DIM * C_DIM, pb2 + (size_t)t * C_DIM,
                        msg_g + (size_t)t * C_DIM, msg_b + (size_t)t * C_DIM,
                        lin_w + (size_t)t * 2 * C_DIM * C_DIM, lin_b + (size_t)t * C_DIM,
                        Hb, Pb, aggb, cntb, new_i);
        }
        // edge type 1: item -> user (dst = user), params [l,1]
        {
            int t = l * 2 + 1;
            launch_conv(cur_i, cur_u, NUn, ei_iu, nE1,
                        pw1 + (size_t)t * C_DIM * C_DIM, pb1 + (size_t)t * C_DIM,
                        pw2 + (size_t)t * C_DIM * C_DIM, pb2 + (size_t)t * C_DIM,
                        msg_g + (size_t)t * C_DIM, msg_b + (size_t)t * C_DIM,
                        lin_w + (size_t)t * 2 * C_DIM * C_DIM, lin_b + (size_t)t * C_DIM,
                        Hb, Pb, aggb, cntb, new_u);
        }

        float* dst_u = (l == Lm - 1) ? out_f : cur_u;
        float* dst_i = (l == Lm - 1) ? (out_f + (size_t)NUn * C_DIM) : cur_i;

        // node-type LN + relu: node_type 0 = user, 1 = item
        int ub = (NUn * 32 + 255) / 256;
        int ib = (NIn * 32 + 255) / 256;
        node_ln_relu_kernel<<<ub, 256>>>(new_u,
                                         node_g + (size_t)(l * 2 + 0) * C_DIM,
                                         node_b + (size_t)(l * 2 + 0) * C_DIM,
                                         dst_u, NUn);
        node_ln_relu_kernel<<<ib, 256>>>(new_i,
                                         node_g + (size_t)(l * 2 + 1) * C_DIM,
                                         node_b + (size_t)(l * 2 + 1) * C_DIM,
                                         dst_i, NIn);
    }
    (void)n_in; (void)out_size;
}

// round 9
// speedup vs baseline: 2.3426x; 2.3426x over previous
#include <cuda_runtime.h>
#include <cuda_bf16.h>
#include <cstdint>

#define C_DIM   256
#define MAXN    100000
#define EPS_LN  1e-5f

typedef __nv_bfloat16 bf16;

// ---------------- device scratch ----------------
__device__ float g_cur_u[MAXN * C_DIM];
__device__ float g_cur_i[MAXN * C_DIM];
__device__ float g_P    [MAXN * C_DIM];
__device__ float g_agg  [MAXN * C_DIM];
__device__ float g_new_u[MAXN * C_DIM];
__device__ float g_new_i[MAXN * C_DIM];
__device__ float g_cnt  [MAXN];

__device__ __align__(16) bf16 g_xu_hi[MAXN * C_DIM];
__device__ __align__(16) bf16 g_xu_lo[MAXN * C_DIM];
__device__ __align__(16) bf16 g_xi_hi[MAXN * C_DIM];
__device__ __align__(16) bf16 g_xi_lo[MAXN * C_DIM];
__device__ __align__(16) bf16 g_h_hi [MAXN * C_DIM];
__device__ __align__(16) bf16 g_h_lo [MAXN * C_DIM];
__device__ __align__(16) bf16 g_a_hi [MAXN * C_DIM];
__device__ __align__(16) bf16 g_a_lo [MAXN * C_DIM];

// per conv: W1T[256,256] | W2T[256,256] | LINT[256,512], K-major rows of N
#define WSTRIDE (65536 + 65536 + 131072)
__device__ __align__(16) bf16 g_w_hi[4 * WSTRIDE];
__device__ __align__(16) bf16 g_w_lo[4 * WSTRIDE];

// ---------------- helpers ----------------
__device__ __forceinline__ uint32_t smem_u32(const void* p) {
    uint32_t a;
    asm("{ .reg .u64 t; cvta.to.shared.u64 t, %1; cvt.u32.u64 %0, t; }" : "=r"(a) : "l"(p));
    return a;
}
__device__ __forceinline__ void cp16(uint32_t s, const void* g) {
    asm volatile("cp.async.cg.shared.global [%0], [%1], 16;" :: "r"(s), "l"(g));
}
__device__ __forceinline__ void cp_commit() { asm volatile("cp.async.commit_group;" ::: "memory"); }
template<int N> __device__ __forceinline__ void cp_wait() {
    asm volatile("cp.async.wait_group %0;" :: "n"(N) : "memory");
}
#define SW128(o) ((o) ^ (((o) >> 3) & 0x70))
__device__ __forceinline__ uint32_t pack_bf2(bf16 a, bf16 b) {
    __nv_bfloat162 t; t.x = a; t.y = b;
    return *reinterpret_cast<uint32_t*>(&t);
}

#define LDSM4(r0, r1, r2, r3, addr) \
    asm volatile("ldmatrix.sync.aligned.m8n8.x4.shared.b16 {%0,%1,%2,%3}, [%4];" \
                 : "=r"(r0), "=r"(r1), "=r"(r2), "=r"(r3) : "r"(addr))

#define MMA16816(d, a, b0, b1) \
    asm volatile("mma.sync.aligned.m16n8k16.row.col.f32.bf16.bf16.f32 " \
                 "{%0,%1,%2,%3}, {%4,%5,%6,%7}, {%8,%9}, {%0,%1,%2,%3};" \
                 : "+f"((d)[0]), "+f"((d)[1]), "+f"((d)[2]), "+f"((d)[3]) \
                 : "r"((a)[0]), "r"((a)[1]), "r"((a)[2]), "r"((a)[3]), \
                   "r"(b0), "r"(b1))

// ---------------- warp-MMA GEMM ----------------
// out[M,256] = A[M,K] @ B^T (+bias); B stored [256,K] K-major bf16 hi/lo.
// A chunks: k<256 from A1 pairs, k>=256 from A2 pairs (both [M,256] row-major).
// Block tile 128(M) x 128(N), 8 warps (2m x 4n), warp tile 64x32, K chunk 64.
// 3-term compensated bf16: Ah*Bh + Ah*Bl + Al*Bh, fp32 register accum.
// EPI 0: fp32 out = D + bias.  EPI 1: relu(D+bias) -> bf16 hi/lo pairs.
#define CHUNK_BYTES 65536       // Ah 16K | Al 16K | Bh 16K | Bl 16K
#define GEMM_SMEM   (2 * CHUNK_BYTES)

__device__ __forceinline__ void gemm_load_chunk(
    uint32_t sbuf, int tid, int m0, int n0, int M, int K, int c,
    const bf16* A1h, const bf16* A1l, const bf16* A2h, const bf16* A2l,
    const bf16* Bh, const bf16* Bl)
{
    const bf16 *ah, *al; int kA;
    if (c < 4) { ah = A1h; al = A1l; kA = c * 64; }
    else       { ah = A2h; al = A2l; kA = (c - 4) * 64; }
    const int kB = c * 64;
#pragma unroll
    for (int i = 0; i < 4; i++) {              // A hi/lo: 128 rows x 128B
        int idx = tid + i * 256;
        int r = idx >> 3, u = idx & 7;
        int rg = min(m0 + r, M - 1);
        uint32_t so = SW128((uint32_t)(r * 128 + u * 16));
        cp16(sbuf + so,         (const char*)(ah + (size_t)rg * C_DIM + kA) + u * 16);
        cp16(sbuf + 16384 + so, (const char*)(al + (size_t)rg * C_DIM + kA) + u * 16);
    }
#pragma unroll
    for (int i = 0; i < 4; i++) {              // B hi/lo: 128 n-rows x 128B
        int idx = tid + i * 256;
        int r = idx >> 3, u = idx & 7;
        uint32_t so = SW128((uint32_t)(r * 128 + u * 16));
        cp16(sbuf + 32768 + so, (const char*)(Bh + (size_t)(n0 + r) * K + kB) + u * 16);
        cp16(sbuf + 49152 + so, (const char*)(Bl + (size_t)(n0 + r) * K + kB) + u * 16);
    }
}

template<int EPI>
__global__ __launch_bounds__(256, 1)
void gemm_mma(const bf16* __restrict__ A1h, const bf16* __restrict__ A1l,
              const bf16* __restrict__ A2h, const bf16* __restrict__ A2l,
              const bf16* __restrict__ Bh,  const bf16* __restrict__ Bl,
              const float* __restrict__ bias,
              float* __restrict__ outF, bf16* __restrict__ outH, bf16* __restrict__ outL,
              int M, int K)
{
    extern __shared__ char smem[];
    const uint32_t sb = smem_u32(smem);
    const int tid  = threadIdx.x;
    const int lane = tid & 31;
    const int wid  = tid >> 5;
    const int wm   = wid >> 2;         // 0..1  (64-row group)
    const int wn   = wid & 3;          // 0..3  (32-col group)
    const int m0   = blockIdx.x * 128;
    const int n0   = blockIdx.y * 128;
    const int nC   = K >> 6;

    // per-lane base offsets (bytes) into SW128 tiles
    const uint32_t aOff = (uint32_t)((wm * 64 + (lane & 15)) * 128 + ((lane >> 4) << 4));
    const uint32_t bOff = (uint32_t)((wn * 32 + (lane & 7) + ((lane >> 4) << 3)) * 128
                                     + (((lane >> 3) & 1) << 4));

    float D[4][4][4];
#pragma unroll
    for (int g = 0; g < 4; g++)
#pragma unroll
        for (int n = 0; n < 4; n++)
#pragma unroll
            for (int q = 0; q < 4; q++) D[g][n][q] = 0.f;

    gemm_load_chunk(sb, tid, m0, n0, M, K, 0, A1h, A1l, A2h, A2l, Bh, Bl);
    cp_commit();

    for (int c = 0; c < nC; c++) {
        if (c + 1 < nC) {
            gemm_load_chunk(sb + (uint32_t)((c + 1) & 1) * CHUNK_BYTES,
                            tid, m0, n0, M, K, c + 1, A1h, A1l, A2h, A2l, Bh, Bl);
            cp_commit();
            cp_wait<1>();
        } else {
            cp_wait<0>();
        }
        __syncthreads();

        const uint32_t base = sb + (uint32_t)(c & 1) * CHUNK_BYTES;
#pragma unroll
        for (int ks = 0; ks < 4; ks++) {
            const uint32_t kb = (uint32_t)(ks * 32);
            uint32_t ah[4][4], al_[4][4];
#pragma unroll
            for (int g = 0; g < 4; g++) {
                uint32_t off = aOff + (uint32_t)(g * 2048) + kb;
                uint32_t sw = SW128(off);
                LDSM4(ah[g][0],  ah[g][1],  ah[g][2],  ah[g][3],  base + sw);
                LDSM4(al_[g][0], al_[g][1], al_[g][2], al_[g][3], base + 16384 + sw);
            }
            uint32_t bh[2][4], bl[2][4];
#pragma unroll
            for (int p = 0; p < 2; p++) {
                uint32_t off = bOff + (uint32_t)(p * 2048) + kb;
                uint32_t sw = SW128(off);
                LDSM4(bh[p][0], bh[p][1], bh[p][2], bh[p][3], base + 32768 + sw);
                LDSM4(bl[p][0], bl[p][1], bl[p][2], bl[p][3], base + 49152 + sw);
            }
#pragma unroll
            for (int g = 0; g < 4; g++) {
#pragma unroll
                for (int n = 0; n < 4; n++) {
                    const int p = n >> 1, rb = (n & 1) * 2;
                    MMA16816(D[g][n], ah[g],  bh[p][rb], bh[p][rb + 1]);
                    MMA16816(D[g][n], ah[g],  bl[p][rb], bl[p][rb + 1]);
                    MMA16816(D[g][n], al_[g], bh[p][rb], bh[p][rb + 1]);
                }
            }
        }
        __syncthreads();
    }

    // ---- epilogue ----
#pragma unroll
    for (int g = 0; g < 4; g++) {
#pragma unroll
        for (int n = 0; n < 4; n++) {
            int r0  = m0 + wm * 64 + g * 16 + (lane >> 2);
            int col = n0 + wn * 32 + n * 8 + (lane & 3) * 2;
            float2 bv = *(const float2*)(bias + col);
            float v0 = D[g][n][0] + bv.x;
            float v1 = D[g][n][1] + bv.y;
            float v2 = D[g][n][2] + bv.x;
            float v3 = D[g][n][3] + bv.y;
            if (EPI == 0) {
                if (r0 < M)
                    *(float2*)(outF + (size_t)r0 * C_DIM + col) = make_float2(v0, v1);
                if (r0 + 8 < M)
                    *(float2*)(outF + (size_t)(r0 + 8) * C_DIM + col) = make_float2(v2, v3);
            } else {
                if (r0 < M) {
                    float a = fmaxf(v0, 0.f), b = fmaxf(v1, 0.f);
                    bf16 h0 = __float2bfloat16(a), h1 = __float2bfloat16(b);
                    size_t o = (size_t)r0 * C_DIM + col;
                    *(uint32_t*)(outH + o) = pack_bf2(h0, h1);
                    *(uint32_t*)(outL + o) = pack_bf2(
                        __float2bfloat16(a - __bfloat162float(h0)),
                        __float2bfloat16(b - __bfloat162float(h1)));
                }
                if (r0 + 8 < M) {
                    float a = fmaxf(v2, 0.f), b = fmaxf(v3, 0.f);
                    bf16 h0 = __float2bfloat16(a), h1 = __float2bfloat16(b);
                    size_t o = (size_t)(r0 + 8) * C_DIM + col;
                    *(uint32_t*)(outH + o) = pack_bf2(h0, h1);
                    *(uint32_t*)(outL + o) = pack_bf2(
                        __float2bfloat16(a - __bfloat162float(h0)),
                        __float2bfloat16(b - __bfloat162float(h1)));
                }
            }
        }
    }
}

// ---------------- aux kernels ----------------
__device__ __forceinline__ float warp_sum(float v) {
#pragma unroll
    for (int o = 16; o > 0; o >>= 1) v += __shfl_xor_sync(0xffffffffu, v, o);
    return v;
}

__global__ void f32_pair_kernel(const float* __restrict__ x,
                                bf16* __restrict__ hi, bf16* __restrict__ lo, int n4)
{
    int idx = blockIdx.x * blockDim.x + threadIdx.x;
    if (idx >= n4) return;
    float4 v = ((const float4*)x)[idx];
    bf16 h0 = __float2bfloat16(v.x), h1 = __float2bfloat16(v.y);
    bf16 h2 = __float2bfloat16(v.z), h3 = __float2bfloat16(v.w);
    *(uint2*)(hi + (size_t)idx * 4) = make_uint2(pack_bf2(h0, h1), pack_bf2(h2, h3));
    *(uint2*)(lo + (size_t)idx * 4) = make_uint2(
        pack_bf2(__float2bfloat16(v.x - __bfloat162float(h0)),
                 __float2bfloat16(v.y - __bfloat162float(h1))),
        pack_bf2(__float2bfloat16(v.z - __bfloat162float(h2)),
                 __float2bfloat16(v.w - __bfloat162float(h3))));
}

// W [K,256] row-major -> out [256,K] K-major bf16 hi/lo
__global__ void convert_w_kernel(const float* __restrict__ W,
                                 bf16* __restrict__ hi, bf16* __restrict__ lo, int K)
{
    int idx = blockIdx.x * blockDim.x + threadIdx.x;
    if (idx >= 256 * K) return;
    int n = idx / K, k = idx - n * K;
    float v = W[(size_t)k * 256 + n];
    bf16 h = __float2bfloat16(v);
    hi[idx] = h;
    lo[idx] = __float2bfloat16(v - __bfloat162float(h));
}

__global__ void edge_msg_kernel(const float* __restrict__ xsrc,
                                const float* __restrict__ Pn,
                                const int* __restrict__ ei,
                                const float* __restrict__ gg,
                                const float* __restrict__ bb,
                                float* __restrict__ agg, float* __restrict__ cnt, int nE)
{
    int w = (blockIdx.x * blockDim.x + threadIdx.x) >> 5;
    int lane = threadIdx.x & 31;
    if (w >= nE) return;
    int s = __ldg(ei + w);
    int d = __ldg(ei + nE + w);
    int c0 = lane << 3;
    const float4* xs = (const float4*)(xsrc + (size_t)s * C_DIM + c0);
    const float4* pp = (const float4*)(Pn + (size_t)d * C_DIM + c0);
    float4 a0 = xs[0], a1 = xs[1], p0 = pp[0], p1 = pp[1];
    float r[8] = {a0.x - p0.x, a0.y - p0.y, a0.z - p0.z, a0.w - p0.w,
                  a1.x - p1.x, a1.y - p1.y, a1.z - p1.z, a1.w - p1.w};
    float s1 = 0.f;
#pragma unroll
    for (int i = 0; i < 8; i++) s1 += r[i];
    float mean = warp_sum(s1) * (1.f / 256.f);
    float s2 = 0.f;
#pragma unroll
    for (int i = 0; i < 8; i++) { float t = r[i] - mean; s2 += t * t; }
    float inv = rsqrtf(warp_sum(s2) * (1.f / 256.f) + EPS_LN);
    float4 g0 = *(const float4*)(gg + c0), g1 = *(const float4*)(gg + c0 + 4);
    float4 e0 = *(const float4*)(bb + c0), e1 = *(const float4*)(bb + c0 + 4);
    float m0v = (r[0] - mean) * inv * g0.x + e0.x;
    float m1v = (r[1] - mean) * inv * g0.y + e0.y;
    float m2v = (r[2] - mean) * inv * g0.z + e0.z;
    float m3v = (r[3] - mean) * inv * g0.w + e0.w;
    float m4v = (r[4] - mean) * inv * g1.x + e1.x;
    float m5v = (r[5] - mean) * inv * g1.y + e1.y;
    float m6v = (r[6] - mean) * inv * g1.z + e1.z;
    float m7v = (r[7] - mean) * inv * g1.w + e1.w;
    float* dstp = agg + (size_t)d * C_DIM + c0;
    asm volatile("red.global.add.v4.f32 [%0], {%1,%2,%3,%4};"
                 :: "l"(dstp), "f"(m0v), "f"(m1v), "f"(m2v), "f"(m3v) : "memory");
    asm volatile("red.global.add.v4.f32 [%0], {%1,%2,%3,%4};"
                 :: "l"(dstp + 4), "f"(m4v), "f"(m5v), "f"(m6v), "f"(m7v) : "memory");
    if (lane == 0) atomicAdd(cnt + d, 1.0f);
}

// agg/max(cnt,1) -> bf16 hi/lo pairs
__global__ void norm_agg_pair_kernel(const float* __restrict__ agg,
                                     const float* __restrict__ cnt,
                                     bf16* __restrict__ hi, bf16* __restrict__ lo, int n)
{
    int idx = blockIdx.x * blockDim.x + threadIdx.x;
    if (idx >= n * 64) return;
    int row = idx >> 6;
    float inv = 1.f / fmaxf(__ldg(cnt + row), 1.f);
    float4 v = ((const float4*)agg)[idx];
    v.x *= inv; v.y *= inv; v.z *= inv; v.w *= inv;
    bf16 h0 = __float2bfloat16(v.x), h1 = __float2bfloat16(v.y);
    bf16 h2 = __float2bfloat16(v.z), h3 = __float2bfloat16(v.w);
    *(uint2*)(hi + (size_t)idx * 4) = make_uint2(pack_bf2(h0, h1), pack_bf2(h2, h3));
    *(uint2*)(lo + (size_t)idx * 4) = make_uint2(
        pack_bf2(__float2bfloat16(v.x - __bfloat162float(h0)),
                 __float2bfloat16(v.y - __bfloat162float(h1))),
        pack_bf2(__float2bfloat16(v.z - __bfloat162float(h2)),
                 __float2bfloat16(v.w - __bfloat162float(h3))));
}

// out = relu(LN(X)*g+b) fp32; optional bf16 hi/lo pairs
__global__ void node_ln_relu_kernel(const float* __restrict__ X,
                                    const float* __restrict__ gg, const float* __restrict__ bb,
                                    float* __restrict__ out,
                                    bf16* __restrict__ hi, bf16* __restrict__ lo, int M)
{
    int w = (blockIdx.x * blockDim.x + threadIdx.x) >> 5;
    int lane = threadIdx.x & 31;
    if (w >= M) return;
    int c0 = lane << 3;
    const float4* xp = (const float4*)(X + (size_t)w * C_DIM + c0);
    float4 a0 = xp[0], a1 = xp[1];
    float r[8] = {a0.x, a0.y, a0.z, a0.w, a1.x, a1.y, a1.z, a1.w};
    float s1 = 0.f;
#pragma unroll
    for (int i = 0; i < 8; i++) s1 += r[i];
    float mean = warp_sum(s1) * (1.f / 256.f);
    float s2 = 0.f;
#pragma unroll
    for (int i = 0; i < 8; i++) { float t = r[i] - mean; s2 += t * t; }
    float inv = rsqrtf(warp_sum(s2) * (1.f / 256.f) + EPS_LN);
    float4 g0 = *(const float4*)(gg + c0), g1 = *(const float4*)(gg + c0 + 4);
    float4 e0 = *(const float4*)(bb + c0), e1 = *(const float4*)(bb + c0 + 4);
    float o[8];
    o[0] = fmaxf((r[0] - mean) * inv * g0.x + e0.x, 0.f);
    o[1] = fmaxf((r[1] - mean) * inv * g0.y + e0.y, 0.f);
    o[2] = fmaxf((r[2] - mean) * inv * g0.z + e0.z, 0.f);
    o[3] = fmaxf((r[3] - mean) * inv * g0.w + e0.w, 0.f);
    o[4] = fmaxf((r[4] - mean) * inv * g1.x + e1.x, 0.f);
    o[5] = fmaxf((r[5] - mean) * inv * g1.y + e1.y, 0.f);
    o[6] = fmaxf((r[6] - mean) * inv * g1.z + e1.z, 0.f);
    o[7] = fmaxf((r[7] - mean) * inv * g1.w + e1.w, 0.f);
    float4* op = (float4*)(out + (size_t)w * C_DIM + c0);
    op[0] = make_float4(o[0], o[1], o[2], o[3]);
    op[1] = make_float4(o[4], o[5], o[6], o[7]);
    if (hi) {
        uint32_t hw[4], lw[4];
#pragma unroll
        for (int p = 0; p < 4; p++) {
            bf16 h0 = __float2bfloat16(o[p * 2]), h1 = __float2bfloat16(o[p * 2 + 1]);
            hw[p] = pack_bf2(h0, h1);
            lw[p] = pack_bf2(__float2bfloat16(o[p * 2] - __bfloat162float(h0)),
                             __float2bfloat16(o[p * 2 + 1] - __bfloat162float(h1)));
        }
        *(uint4*)(hi + (size_t)w * C_DIM + c0) = make_uint4(hw[0], hw[1], hw[2], hw[3]);
        *(uint4*)(lo + (size_t)w * C_DIM + c0) = make_uint4(lw[0], lw[1], lw[2], lw[3]);
    }
}

// ---------------- host ----------------
extern "C" void kernel_launch(void* const* d_in, const int* in_sizes, int n_in,
                              void* d_out, int out_size)
{
    const float* x_user = (const float*)d_in[0];
    const float* x_item = (const float*)d_in[1];
    const float* pw1    = (const float*)d_in[2];
    const float* pb1    = (const float*)d_in[3];
    const float* pw2    = (const float*)d_in[4];
    const float* pb2    = (const float*)d_in[5];
    const float* msg_g  = (const float*)d_in[6];
    const float* msg_b  = (const float*)d_in[7];
    const float* lin_w  = (const float*)d_in[8];
    const float* lin_b  = (const float*)d_in[9];
    const float* node_g = (const float*)d_in[10];
    const float* node_b = (const float*)d_in[11];
    const int*   ei_ui  = (const int*)d_in[12];
    const int*   ei_iu  = (const int*)d_in[13];

    const int NUn = in_sizes[0] / C_DIM;
    const int NIn = in_sizes[1] / C_DIM;
    const int nE0 = in_sizes[12] / 2;
    const int nE1 = in_sizes[13] / 2;
    const int Lm = 2;

    float *cur_u, *cur_i, *Pb, *aggb, *cntb, *new_u, *new_i;
    bf16 *xu_hi, *xu_lo, *xi_hi, *xi_lo, *h_hi, *h_lo, *a_hi, *a_lo, *w_hi, *w_lo;
    cudaGetSymbolAddress((void**)&cur_u, g_cur_u);
    cudaGetSymbolAddress((void**)&cur_i, g_cur_i);
    cudaGetSymbolAddress((void**)&Pb, g_P);
    cudaGetSymbolAddress((void**)&aggb, g_agg);
    cudaGetSymbolAddress((void**)&cntb, g_cnt);
    cudaGetSymbolAddress((void**)&new_u, g_new_u);
    cudaGetSymbolAddress((void**)&new_i, g_new_i);
    cudaGetSymbolAddress((void**)&xu_hi, g_xu_hi);
    cudaGetSymbolAddress((void**)&xu_lo, g_xu_lo);
    cudaGetSymbolAddress((void**)&xi_hi, g_xi_hi);
    cudaGetSymbolAddress((void**)&xi_lo, g_xi_lo);
    cudaGetSymbolAddress((void**)&h_hi, g_h_hi);
    cudaGetSymbolAddress((void**)&h_lo, g_h_lo);
    cudaGetSymbolAddress((void**)&a_hi, g_a_hi);
    cudaGetSymbolAddress((void**)&a_lo, g_a_lo);
    cudaGetSymbolAddress((void**)&w_hi, g_w_hi);
    cudaGetSymbolAddress((void**)&w_lo, g_w_lo);

    cudaFuncSetAttribute(gemm_mma<0>, cudaFuncAttributeMaxDynamicSharedMemorySize, GEMM_SMEM);
    cudaFuncSetAttribute(gemm_mma<1>, cudaFuncAttributeMaxDynamicSharedMemorySize, GEMM_SMEM);

    // weights -> transposed bf16 pairs
    for (int t = 0; t < 4; t++) {
        size_t wo = (size_t)t * WSTRIDE;
        convert_w_kernel<<<256, 256>>>(pw1 + (size_t)t * 65536, w_hi + wo, w_lo + wo, 256);
        convert_w_kernel<<<256, 256>>>(pw2 + (size_t)t * 65536, w_hi + wo + 65536, w_lo + wo + 65536, 256);
        convert_w_kernel<<<512, 256>>>(lin_w + (size_t)t * 131072, w_hi + wo + 131072, w_lo + wo + 131072, 512);
    }
    // input feature pairs
    f32_pair_kernel<<<(NUn * 64 + 255) / 256, 256>>>(x_user, xu_hi, xu_lo, NUn * 64);
    f32_pair_kernel<<<(NIn * 64 + 255) / 256, 256>>>(x_item, xi_hi, xi_lo, NIn * 64);

    const float* cu_f = x_user;
    const float* ci_f = x_item;
    float* out_f = (float*)d_out;

    for (int l = 0; l < Lm; l++) {
        bool last = (l == Lm - 1);
        // ---- conv: dst = item (params [l,0]) ----
        {
            int t = l * 2 + 0;
            size_t wo = (size_t)t * WSTRIDE;
            dim3 gI((NIn + 127) / 128, 2);
            gemm_mma<1><<<gI, 256, GEMM_SMEM>>>(xi_hi, xi_lo, (bf16*)0, (bf16*)0,
                w_hi + wo, w_lo + wo, pb1 + (size_t)t * C_DIM, (float*)0, h_hi, h_lo, NIn, 256);
            gemm_mma<0><<<gI, 256, GEMM_SMEM>>>(h_hi, h_lo, (bf16*)0, (bf16*)0,
                w_hi + wo + 65536, w_lo + wo + 65536, pb2 + (size_t)t * C_DIM, Pb, (bf16*)0, (bf16*)0, NIn, 256);
            cudaMemsetAsync(aggb, 0, (size_t)NIn * C_DIM * sizeof(float));
            cudaMemsetAsync(cntb, 0, (size_t)NIn * sizeof(float));
            edge_msg_kernel<<<(nE0 * 32 + 255) / 256, 256>>>(cu_f, Pb, ei_ui,
                msg_g + (size_t)t * C_DIM, msg_b + (size_t)t * C_DIM, aggb, cntb, nE0);
            norm_agg_pair_kernel<<<(NIn * 64 + 255) / 256, 256>>>(aggb, cntb, a_hi, a_lo, NIn);
            gemm_mma<0><<<gI, 256, GEMM_SMEM>>>(xi_hi, xi_lo, a_hi, a_lo,
                w_hi + wo + 131072, w_lo + wo + 131072, lin_b + (size_t)t * C_DIM, new_i, (bf16*)0, (bf16*)0, NIn, 512);
        }
        // ---- conv: dst = user (params [l,1]) ----
        {
            int t = l * 2 + 1;
            size_t wo = (size_t)t * WSTRIDE;
            dim3 gU((NUn + 127) / 128, 2);
            gemm_mma<1><<<gU, 256, GEMM_SMEM>>>(xu_hi, xu_lo, (bf16*)0, (bf16*)0,
                w_hi + wo, w_lo + wo, pb1 + (size_t)t * C_DIM, (float*)0, h_hi, h_lo, NUn, 256);
            gemm_mma<0><<<gU, 256, GEMM_SMEM>>>(h_hi, h_lo, (bf16*)0, (bf16*)0,
                w_hi + wo + 65536, w_lo + wo + 65536, pb2 + (size_t)t * C_DIM, Pb, (bf16*)0, (bf16*)0, NUn, 256);
            cudaMemsetAsync(aggb, 0, (size_t)NUn * C_DIM * sizeof(float));
            cudaMemsetAsync(cntb, 0, (size_t)NUn * sizeof(float));
            edge_msg_kernel<<<(nE1 * 32 + 255) / 256, 256>>>(ci_f, Pb, ei_iu,
                msg_g + (size_t)t * C_DIM, msg_b + (size_t)t * C_DIM, aggb, cntb, nE1);
            norm_agg_pair_kernel<<<(NUn * 64 + 255) / 256, 256>>>(aggb, cntb, a_hi, a_lo, NUn);
            gemm_mma<0><<<gU, 256, GEMM_SMEM>>>(xu_hi, xu_lo, a_hi, a_lo,
                w_hi + wo + 131072, w_lo + wo + 131072, lin_b + (size_t)t * C_DIM, new_u, (bf16*)0, (bf16*)0, NUn, 512);
        }
        // ---- node LN + relu ----
        float* du = last ? out_f : cur_u;
        float* di = last ? (out_f + (size_t)NUn * C_DIM) : cur_i;
        node_ln_relu_kernel<<<(NUn * 32 + 255) / 256, 256>>>(new_u,
            node_g + (size_t)(l * 2 + 0) * C_DIM, node_b + (size_t)(l * 2 + 0) * C_DIM,
            du, last ? (bf16*)0 : xu_hi, last ? (bf16*)0 : xu_lo, NUn);
        node_ln_relu_kernel<<<(NIn * 32 + 255) / 256, 256>>>(new_i,
            node_g + (size_t)(l * 2 + 1) * C_DIM, node_b + (size_t)(l * 2 + 1) * C_DIM,
            di, last ? (bf16*)0 : xi_hi, last ? (bf16*)0 : xi_lo, NIn);
        cu_f = cur_u;
        ci_f = cur_i;
    }
    (void)n_in; (void)out_size;
}

// round 10
// speedup vs baseline: 2.8115x; 1.2002x over previous
#include <cuda_runtime.h>
#include <cuda_fp16.h>
#include <cstdint>

#define C_DIM   256
#define MAXN    100000
#define EPS_LN  1e-5f

typedef __half f16;

// ---------------- device scratch ----------------
__device__ float g_cur_u[MAXN * C_DIM];
__device__ float g_cur_i[MAXN * C_DIM];
__device__ float g_P    [MAXN * C_DIM];
__device__ float g_agg  [MAXN * C_DIM];
__device__ float g_new_u[MAXN * C_DIM];
__device__ float g_new_i[MAXN * C_DIM];
__device__ float g_cnt  [MAXN];

__device__ __align__(16) f16 g_xu_f[MAXN * C_DIM];
__device__ __align__(16) f16 g_xi_f[MAXN * C_DIM];
__device__ __align__(16) f16 g_h_f [MAXN * C_DIM];
__device__ __align__(16) f16 g_a_f [MAXN * C_DIM];

// per conv: BCAT[512,256] (W1T rows 0-255 | WxT rows 256-511) | W2T[256,256] | WaT[256,256]
// all K-major [n, k], K = 256
#define WSTRIDE (1024 * 256)
__device__ __align__(16) f16 g_w_hi[4 * WSTRIDE];
__device__ __align__(16) f16 g_w_lo[4 * WSTRIDE];

// ---------------- helpers ----------------
__device__ __forceinline__ uint32_t smem_u32(const void* p) {
    uint32_t a;
    asm("{ .reg .u64 t; cvta.to.shared.u64 t, %1; cvt.u32.u64 %0, t; }" : "=r"(a) : "l"(p));
    return a;
}
__device__ __forceinline__ void cp16(uint32_t s, const void* g) {
    asm volatile("cp.async.cg.shared.global [%0], [%1], 16;" :: "r"(s), "l"(g));
}
__device__ __forceinline__ void cp_commit() { asm volatile("cp.async.commit_group;" ::: "memory"); }
template<int N> __device__ __forceinline__ void cp_wait() {
    asm volatile("cp.async.wait_group %0;" :: "n"(N) : "memory");
}
#define SW128(o) ((o) ^ (((o) >> 3) & 0x70))

__device__ __forceinline__ uint32_t pack_h2(float a, float b) {
    __half2 t = __halves2half2(__float2half_rn(a), __float2half_rn(b));
    return *reinterpret_cast<uint32_t*>(&t);
}

#define LDSM4(r0, r1, r2, r3, addr) \
    asm volatile("ldmatrix.sync.aligned.m8n8.x4.shared.b16 {%0,%1,%2,%3}, [%4];" \
                 : "=r"(r0), "=r"(r1), "=r"(r2), "=r"(r3) : "r"(addr))

#define MMA16816F(d, a, b0, b1) \
    asm volatile("mma.sync.aligned.m16n8k16.row.col.f32.f16.f16.f32 " \
                 "{%0,%1,%2,%3}, {%4,%5,%6,%7}, {%8,%9}, {%0,%1,%2,%3};" \
                 : "+f"((d)[0]), "+f"((d)[1]), "+f"((d)[2]), "+f"((d)[3]) \
                 : "r"((a)[0]), "r"((a)[1]), "r"((a)[2]), "r"((a)[3]), \
                   "r"(b0), "r"(b1))

// ---------------- warp-MMA GEMM (fp16 2-term) ----------------
// out[M, *] = A[M,256] @ B^T; B stored [NB,256] K-major fp16 hi/lo.
// Block tile 128(M) x 128(N), 8 warps (2m x 4n), warp tile 64x32, K chunk 64.
// 2-term: Af*Bh + Af*Bl, fp32 register accum.
// EPI 0: outF = D + bias1                      (P = H@W2 + b2)
// EPI 1: outF += D                              (new += agg@Wa)
// EPI 3: cols<256 -> outH = f16(relu(D+bias1)); cols>=256 -> outF = D + bias2
#define CHUNK_BYTES 49152       // A 16K | Bh 16K | Bl 16K
#define GEMM_SMEM   (2 * CHUNK_BYTES)

__device__ __forceinline__ void gemm_load_chunk(
    uint32_t sbuf, int tid, int m0, int n0, int M, int c,
    const f16* Af, const f16* Bh, const f16* Bl)
{
    const int k0 = c * 64;
#pragma unroll
    for (int i = 0; i < 4; i++) {              // A: 128 rows x 128B
        int idx = tid + i * 256;
        int r = idx >> 3, u = idx & 7;
        int rg = min(m0 + r, M - 1);
        uint32_t so = SW128((uint32_t)(r * 128 + u * 16));
        cp16(sbuf + so, (const char*)(Af + (size_t)rg * C_DIM + k0) + u * 16);
    }
#pragma unroll
    for (int i = 0; i < 4; i++) {              // B hi/lo: 128 n-rows x 128B
        int idx = tid + i * 256;
        int r = idx >> 3, u = idx & 7;
        uint32_t so = SW128((uint32_t)(r * 128 + u * 16));
        cp16(sbuf + 16384 + so, (const char*)(Bh + (size_t)(n0 + r) * C_DIM + k0) + u * 16);
        cp16(sbuf + 32768 + so, (const char*)(Bl + (size_t)(n0 + r) * C_DIM + k0) + u * 16);
    }
}

template<int EPI>
__global__ __launch_bounds__(256, 2)
void gemm_mma(const f16* __restrict__ Af,
              const f16* __restrict__ Bh, const f16* __restrict__ Bl,
              const float* __restrict__ bias1, const float* __restrict__ bias2,
              float* __restrict__ outF, f16* __restrict__ outH, int M)
{
    extern __shared__ char smem[];
    const uint32_t sb = smem_u32(smem);
    const int tid  = threadIdx.x;
    const int lane = tid & 31;
    const int wid  = tid >> 5;
    const int wm   = wid >> 2;         // 0..1
    const int wn   = wid & 3;          // 0..3
    const int m0   = blockIdx.x * 128;
    const int n0   = blockIdx.y * 128;

    const uint32_t aOff = (uint32_t)((wm * 64 + (lane & 15)) * 128 + ((lane >> 4) << 4));
    const uint32_t bOff = (uint32_t)((wn * 32 + (lane & 7) + ((lane >> 4) << 3)) * 128
                                     + (((lane >> 3) & 1) << 4));

    float D[4][4][4];
#pragma unroll
    for (int g = 0; g < 4; g++)
#pragma unroll
        for (int n = 0; n < 4; n++)
#pragma unroll
            for (int q = 0; q < 4; q++) D[g][n][q] = 0.f;

    gemm_load_chunk(sb, tid, m0, n0, M, 0, Af, Bh, Bl);
    cp_commit();

#pragma unroll
    for (int c = 0; c < 4; c++) {
        if (c + 1 < 4) {
            gemm_load_chunk(sb + (uint32_t)((c + 1) & 1) * CHUNK_BYTES,
                            tid, m0, n0, M, c + 1, Af, Bh, Bl);
            cp_commit();
            cp_wait<1>();
        } else {
            cp_wait<0>();
        }
        __syncthreads();

        const uint32_t base = sb + (uint32_t)(c & 1) * CHUNK_BYTES;
#pragma unroll
        for (int ks = 0; ks < 4; ks++) {
            const uint32_t kb = (uint32_t)(ks * 32);
            uint32_t af[4][4];
#pragma unroll
            for (int g = 0; g < 4; g++) {
                uint32_t sw = SW128(aOff + (uint32_t)(g * 2048) + kb);
                LDSM4(af[g][0], af[g][1], af[g][2], af[g][3], base + sw);
            }
            uint32_t bh[2][4], bl[2][4];
#pragma unroll
            for (int p = 0; p < 2; p++) {
                uint32_t sw = SW128(bOff + (uint32_t)(p * 2048) + kb);
                LDSM4(bh[p][0], bh[p][1], bh[p][2], bh[p][3], base + 16384 + sw);
                LDSM4(bl[p][0], bl[p][1], bl[p][2], bl[p][3], base + 32768 + sw);
            }
#pragma unroll
            for (int g = 0; g < 4; g++) {
#pragma unroll
                for (int n = 0; n < 4; n++) {
                    const int p = n >> 1, rb = (n & 1) * 2;
                    MMA16816F(D[g][n], af[g], bh[p][rb], bh[p][rb + 1]);
                    MMA16816F(D[g][n], af[g], bl[p][rb], bl[p][rb + 1]);
                }
            }
        }
        __syncthreads();
    }

    // ---- epilogue ----
#pragma unroll
    for (int g = 0; g < 4; g++) {
#pragma unroll
        for (int n = 0; n < 4; n++) {
            int r0  = m0 + wm * 64 + g * 16 + (lane >> 2);
            int col = n0 + wn * 32 + n * 8 + (lane & 3) * 2;
            if (EPI == 0) {
                float2 bv = *(const float2*)(bias1 + col);
                if (r0 < M)
                    *(float2*)(outF + (size_t)r0 * C_DIM + col) =
                        make_float2(D[g][n][0] + bv.x, D[g][n][1] + bv.y);
                if (r0 + 8 < M)
                    *(float2*)(outF + (size_t)(r0 + 8) * C_DIM + col) =
                        make_float2(D[g][n][2] + bv.x, D[g][n][3] + bv.y);
            } else if (EPI == 1) {
                if (r0 < M) {
                    float2* p = (float2*)(outF + (size_t)r0 * C_DIM + col);
                    float2 o = *p;
                    *p = make_float2(o.x + D[g][n][0], o.y + D[g][n][1]);
                }
                if (r0 + 8 < M) {
                    float2* p = (float2*)(outF + (size_t)(r0 + 8) * C_DIM + col);
                    float2 o = *p;
                    *p = make_float2(o.x + D[g][n][2], o.y + D[g][n][3]);
                }
            } else {  // EPI 3
                if (col < 256) {
                    float2 bv = *(const float2*)(bias1 + col);
                    if (r0 < M)
                        *(uint32_t*)(outH + (size_t)r0 * C_DIM + col) =
                            pack_h2(fmaxf(D[g][n][0] + bv.x, 0.f),
                                    fmaxf(D[g][n][1] + bv.y, 0.f));
                    if (r0 + 8 < M)
                        *(uint32_t*)(outH + (size_t)(r0 + 8) * C_DIM + col) =
                            pack_h2(fmaxf(D[g][n][2] + bv.x, 0.f),
                                    fmaxf(D[g][n][3] + bv.y, 0.f));
                } else {
                    int cf = col - 256;
                    float2 bv = *(const float2*)(bias2 + cf);
                    if (r0 < M)
                        *(float2*)(outF + (size_t)r0 * C_DIM + cf) =
                            make_float2(D[g][n][0] + bv.x, D[g][n][1] + bv.y);
                    if (r0 + 8 < M)
                        *(float2*)(outF + (size_t)(r0 + 8) * C_DIM + cf) =
                            make_float2(D[g][n][2] + bv.x, D[g][n][3] + bv.y);
                }
            }
        }
    }
}

// ---------------- aux kernels ----------------
__device__ __forceinline__ float warp_sum(float v) {
#pragma unroll
    for (int o = 16; o > 0; o >>= 1) v += __shfl_xor_sync(0xffffffffu, v, o);
    return v;
}

__global__ void f32_to_f16_kernel(const float* __restrict__ x,
                                  f16* __restrict__ out, int n4)
{
    int idx = blockIdx.x * blockDim.x + threadIdx.x;
    if (idx >= n4) return;
    float4 v = ((const float4*)x)[idx];
    *(uint2*)(out + (size_t)idx * 4) = make_uint2(pack_h2(v.x, v.y), pack_h2(v.z, v.w));
}

// W [256 rows(k), 256 cols(n)] row-major -> dst[n*256+k] fp16 hi/lo
__global__ void convert_w_kernel(const float* __restrict__ W,
                                 f16* __restrict__ hi, f16* __restrict__ lo)
{
    int idx = blockIdx.x * blockDim.x + threadIdx.x;
    if (idx >= 65536) return;
    int n = idx >> 8, k = idx & 255;
    float v = W[(size_t)k * 256 + n];
    f16 h = __float2half_rn(v);
    hi[idx] = h;
    lo[idx] = __float2half_rn(v - __half2float(h));
}

__global__ void edge_msg_kernel(const float* __restrict__ xsrc,
                                const float* __restrict__ Pn,
                                const int* __restrict__ ei,
                                const float* __restrict__ gg,
                                const float* __restrict__ bb,
                                float* __restrict__ agg, float* __restrict__ cnt, int nE)
{
    int w = (blockIdx.x * blockDim.x + threadIdx.x) >> 5;
    int lane = threadIdx.x & 31;
    if (w >= nE) return;
    int s = __ldg(ei + w);
    int d = __ldg(ei + nE + w);
    int c0 = lane << 3;
    const float4* xs = (const float4*)(xsrc + (size_t)s * C_DIM + c0);
    const float4* pp = (const float4*)(Pn + (size_t)d * C_DIM + c0);
    float4 a0 = xs[0], a1 = xs[1], p0 = pp[0], p1 = pp[1];
    float r[8] = {a0.x - p0.x, a0.y - p0.y, a0.z - p0.z, a0.w - p0.w,
                  a1.x - p1.x, a1.y - p1.y, a1.z - p1.z, a1.w - p1.w};
    float s1 = 0.f;
#pragma unroll
    for (int i = 0; i < 8; i++) s1 += r[i];
    float mean = warp_sum(s1) * (1.f / 256.f);
    float s2 = 0.f;
#pragma unroll
    for (int i = 0; i < 8; i++) { float t = r[i] - mean; s2 += t * t; }
    float inv = rsqrtf(warp_sum(s2) * (1.f / 256.f) + EPS_LN);
    float4 g0 = *(const float4*)(gg + c0), g1 = *(const float4*)(gg + c0 + 4);
    float4 e0 = *(const float4*)(bb + c0), e1 = *(const float4*)(bb + c0 + 4);
    float m0v = (r[0] - mean) * inv * g0.x + e0.x;
    float m1v = (r[1] - mean) * inv * g0.y + e0.y;
    float m2v = (r[2] - mean) * inv * g0.z + e0.z;
    float m3v = (r[3] - mean) * inv * g0.w + e0.w;
    float m4v = (r[4] - mean) * inv * g1.x + e1.x;
    float m5v = (r[5] - mean) * inv * g1.y + e1.y;
    float m6v = (r[6] - mean) * inv * g1.z + e1.z;
    float m7v = (r[7] - mean) * inv * g1.w + e1.w;
    float* dstp = agg + (size_t)d * C_DIM + c0;
    asm volatile("red.global.add.v4.f32 [%0], {%1,%2,%3,%4};"
                 :: "l"(dstp), "f"(m0v), "f"(m1v), "f"(m2v), "f"(m3v) : "memory");
    asm volatile("red.global.add.v4.f32 [%0], {%1,%2,%3,%4};"
                 :: "l"(dstp + 4), "f"(m4v), "f"(m5v), "f"(m6v), "f"(m7v) : "memory");
    if (lane == 0) atomicAdd(cnt + d, 1.0f);
}

// agg/max(cnt,1) -> fp16
__global__ void norm_agg_f16_kernel(const float* __restrict__ agg,
                                    const float* __restrict__ cnt,
                                    f16* __restrict__ out, int n)
{
    int idx = blockIdx.x * blockDim.x + threadIdx.x;
    if (idx >= n * 64) return;
    int row = idx >> 6;
    float inv = 1.f / fmaxf(__ldg(cnt + row), 1.f);
    float4 v = ((const float4*)agg)[idx];
    *(uint2*)(out + (size_t)idx * 4) =
        make_uint2(pack_h2(v.x * inv, v.y * inv), pack_h2(v.z * inv, v.w * inv));
}

// out = relu(LN(X)*g+b) fp32; optional fp16 copy for next layer
__global__ void node_ln_relu_kernel(const float* __restrict__ X,
                                    const float* __restrict__ gg, const float* __restrict__ bb,
                                    float* __restrict__ out, f16* __restrict__ outh, int M)
{
    int w = (blockIdx.x * blockDim.x + threadIdx.x) >> 5;
    int lane = threadIdx.x & 31;
    if (w >= M) return;
    int c0 = lane << 3;
    const float4* xp = (const float4*)(X + (size_t)w * C_DIM + c0);
    float4 a0 = xp[0], a1 = xp[1];
    float r[8] = {a0.x, a0.y, a0.z, a0.w, a1.x, a1.y, a1.z, a1.w};
    float s1 = 0.f;
#pragma unroll
    for (int i = 0; i < 8; i++) s1 += r[i];
    float mean = warp_sum(s1) * (1.f / 256.f);
    float s2 = 0.f;
#pragma unroll
    for (int i = 0; i < 8; i++) { float t = r[i] - mean; s2 += t * t; }
    float inv = rsqrtf(warp_sum(s2) * (1.f / 256.f) + EPS_LN);
    float4 g0 = *(const float4*)(gg + c0), g1 = *(const float4*)(gg + c0 + 4);
    float4 e0 = *(const float4*)(bb + c0), e1 = *(const float4*)(bb + c0 + 4);
    float o[8];
    o[0] = fmaxf((r[0] - mean) * inv * g0.x + e0.x, 0.f);
    o[1] = fmaxf((r[1] - mean) * inv * g0.y + e0.y, 0.f);
    o[2] = fmaxf((r[2] - mean) * inv * g0.z + e0.z, 0.f);
    o[3] = fmaxf((r[3] - mean) * inv * g0.w + e0.w, 0.f);
    o[4] = fmaxf((r[4] - mean) * inv * g1.x + e1.x, 0.f);
    o[5] = fmaxf((r[5] - mean) * inv * g1.y + e1.y, 0.f);
    o[6] = fmaxf((r[6] - mean) * inv * g1.z + e1.z, 0.f);
    o[7] = fmaxf((r[7] - mean) * inv * g1.w + e1.w, 0.f);
    float4* op = (float4*)(out + (size_t)w * C_DIM + c0);
    op[0] = make_float4(o[0], o[1], o[2], o[3]);
    op[1] = make_float4(o[4], o[5], o[6], o[7]);
    if (outh) {
        *(uint4*)(outh + (size_t)w * C_DIM + c0) =
            make_uint4(pack_h2(o[0], o[1]), pack_h2(o[2], o[3]),
                       pack_h2(o[4], o[5]), pack_h2(o[6], o[7]));
    }
}

// ---------------- host ----------------
extern "C" void kernel_launch(void* const* d_in, const int* in_sizes, int n_in,
                              void* d_out, int out_size)
{
    const float* x_user = (const float*)d_in[0];
    const float* x_item = (const float*)d_in[1];
    const float* pw1    = (const float*)d_in[2];
    const float* pb1    = (const float*)d_in[3];
    const float* pw2    = (const float*)d_in[4];
    const float* pb2    = (const float*)d_in[5];
    const float* msg_g  = (const float*)d_in[6];
    const float* msg_b  = (const float*)d_in[7];
    const float* lin_w  = (const float*)d_in[8];
    const float* lin_b  = (const float*)d_in[9];
    const float* node_g = (const float*)d_in[10];
    const float* node_b = (const float*)d_in[11];
    const int*   ei_ui  = (const int*)d_in[12];
    const int*   ei_iu  = (const int*)d_in[13];

    const int NUn = in_sizes[0] / C_DIM;
    const int NIn = in_sizes[1] / C_DIM;
    const int nE0 = in_sizes[12] / 2;
    const int nE1 = in_sizes[13] / 2;
    const int Lm = 2;

    float *cur_u, *cur_i, *Pb, *aggb, *cntb, *new_u, *new_i;
    f16 *xu_f, *xi_f, *h_f, *a_f, *w_hi, *w_lo;
    cudaGetSymbolAddress((void**)&cur_u, g_cur_u);
    cudaGetSymbolAddress((void**)&cur_i, g_cur_i);
    cudaGetSymbolAddress((void**)&Pb, g_P);
    cudaGetSymbolAddress((void**)&aggb, g_agg);
    cudaGetSymbolAddress((void**)&cntb, g_cnt);
    cudaGetSymbolAddress((void**)&new_u, g_new_u);
    cudaGetSymbolAddress((void**)&new_i, g_new_i);
    cudaGetSymbolAddress((void**)&xu_f, g_xu_f);
    cudaGetSymbolAddress((void**)&xi_f, g_xi_f);
    cudaGetSymbolAddress((void**)&h_f, g_h_f);
    cudaGetSymbolAddress((void**)&a_f, g_a_f);
    cudaGetSymbolAddress((void**)&w_hi, g_w_hi);
    cudaGetSymbolAddress((void**)&w_lo, g_w_lo);

    cudaFuncSetAttribute(gemm_mma<0>, cudaFuncAttributeMaxDynamicSharedMemorySize, GEMM_SMEM);
    cudaFuncSetAttribute(gemm_mma<1>, cudaFuncAttributeMaxDynamicSharedMemorySize, GEMM_SMEM);
    cudaFuncSetAttribute(gemm_mma<3>, cudaFuncAttributeMaxDynamicSharedMemorySize, GEMM_SMEM);

    // weights -> transposed fp16 hi/lo
    // layout per conv t: BCAT rows 0-255 = W1T, rows 256-511 = WxT,
    //                    rows 512-767 = W2T, rows 768-1023 = WaT
    for (int t = 0; t < 4; t++) {
        size_t wo = (size_t)t * WSTRIDE;
        convert_w_kernel<<<256, 256>>>(pw1 + (size_t)t * 65536, w_hi + wo, w_lo + wo);
        convert_w_kernel<<<256, 256>>>(lin_w + (size_t)t * 131072,            // Wx (rows 0-255 of lin)
                                       w_hi + wo + 65536, w_lo + wo + 65536);
        convert_w_kernel<<<256, 256>>>(pw2 + (size_t)t * 65536,
                                       w_hi + wo + 131072, w_lo + wo + 131072);
        convert_w_kernel<<<256, 256>>>(lin_w + (size_t)t * 131072 + 65536,    // Wa (rows 256-511)
                                       w_hi + wo + 196608, w_lo + wo + 196608);
    }
    f32_to_f16_kernel<<<(NUn * 64 + 255) / 256, 256>>>(x_user, xu_f, NUn * 64);
    f32_to_f16_kernel<<<(NIn * 64 + 255) / 256, 256>>>(x_item, xi_f, NIn * 64);

    const float* cu_f = x_user;
    const float* ci_f = x_item;
    float* out_f = (float*)d_out;

    for (int l = 0; l < Lm; l++) {
        bool last = (l == Lm - 1);
        // ---- conv: dst = item (params [l,0]) ----
        {
            int t = l * 2 + 0;
            size_t wo = (size_t)t * WSTRIDE;
            dim3 g4((NIn + 127) / 128, 4), g2((NIn + 127) / 128, 2);
            // H = f16(relu(x@W1+b1)); new = x@Wx + lin_b   (fused N=512)
            gemm_mma<3><<<g4, 256, GEMM_SMEM>>>(xi_f, w_hi + wo, w_lo + wo,
                pb1 + (size_t)t * C_DIM, lin_b + (size_t)t * C_DIM, new_i, h_f, NIn);
            // P = H@W2 + b2
            gemm_mma<0><<<g2, 256, GEMM_SMEM>>>(h_f, w_hi + wo + 131072, w_lo + wo + 131072,
                pb2 + (size_t)t * C_DIM, (float*)0, Pb, (f16*)0, NIn);
            cudaMemsetAsync(aggb, 0, (size_t)NIn * C_DIM * sizeof(float));
            cudaMemsetAsync(cntb, 0, (size_t)NIn * sizeof(float));
            edge_msg_kernel<<<(nE0 * 32 + 255) / 256, 256>>>(cu_f, Pb, ei_ui,
                msg_g + (size_t)t * C_DIM, msg_b + (size_t)t * C_DIM, aggb, cntb, nE0);
            norm_agg_f16_kernel<<<(NIn * 64 + 255) / 256, 256>>>(aggb, cntb, a_f, NIn);
            // new += agg@Wa
            gemm_mma<1><<<g2, 256, GEMM_SMEM>>>(a_f, w_hi + wo + 196608, w_lo + wo + 196608,
                (float*)0, (float*)0, new_i, (f16*)0, NIn);
        }
        // ---- conv: dst = user (params [l,1]) ----
        {
            int t = l * 2 + 1;
            size_t wo = (size_t)t * WSTRIDE;
            dim3 g4((NUn + 127) / 128, 4), g2((NUn + 127) / 128, 2);
            gemm_mma<3><<<g4, 256, GEMM_SMEM>>>(xu_f, w_hi + wo, w_lo + wo,
                pb1 + (size_t)t * C_DIM, lin_b + (size_t)t * C_DIM, new_u, h_f, NUn);
            gemm_mma<0><<<g2, 256, GEMM_SMEM>>>(h_f, w_hi + wo + 131072, w_lo + wo + 131072,
                pb2 + (size_t)t * C_DIM, (float*)0, Pb, (f16*)0, NUn);
            cudaMemsetAsync(aggb, 0, (size_t)NUn * C_DIM * sizeof(float));
            cudaMemsetAsync(cntb, 0, (size_t)NUn * sizeof(float));
            edge_msg_kernel<<<(nE1 * 32 + 255) / 256, 256>>>(ci_f, Pb, ei_iu,
                msg_g + (size_t)t * C_DIM, msg_b + (size_t)t * C_DIM, aggb, cntb, nE1);
            norm_agg_f16_kernel<<<(NUn * 64 + 255) / 256, 256>>>(aggb, cntb, a_f, NUn);
            gemm_mma<1><<<g2, 256, GEMM_SMEM>>>(a_f, w_hi + wo + 196608, w_lo + wo + 196608,
                (float*)0, (float*)0, new_u, (f16*)0, NUn);
        }
        // ---- node LN + relu ----
        float* du = last ? out_f : cur_u;
        float* di = last ? (out_f + (size_t)NUn * C_DIM) : cur_i;
        node_ln_relu_kernel<<<(NUn * 32 + 255) / 256, 256>>>(new_u,
            node_g + (size_t)(l * 2 + 0) * C_DIM, node_b + (size_t)(l * 2 + 0) * C_DIM,
            du, last ? (f16*)0 : xu_f, NUn);
        node_ln_relu_kernel<<<(NIn * 32 + 255) / 256, 256>>>(new_i,
            node_g + (size_t)(l * 2 + 1) * C_DIM, node_b + (size_t)(l * 2 + 1) * C_DIM,
            di, last ? (f16*)0 : xi_f, NIn);
        cu_f = cur_u;
        ci_f = cur_i;
    }
    (void)n_in; (void)out_size;
}

// round 11
// speedup vs baseline: 3.7586x; 1.3368x over previous
#include <cuda_runtime.h>
#include <cuda_fp16.h>
#include <cstdint>

#define C_DIM   256
#define MAXN    100000
#define EPS_LN  1e-5f

typedef __half f16;

// ---------------- device scratch ----------------
__device__ float g_agg  [MAXN * C_DIM];
__device__ float g_new_u[MAXN * C_DIM];
__device__ float g_new_i[MAXN * C_DIM];
__device__ float g_cnt_i[MAXN];   // in-degree of items (ei_ui dst)
__device__ float g_cnt_u[MAXN];   // in-degree of users (ei_iu dst)

__device__ __align__(16) f16 g_xu_f[MAXN * C_DIM];
__device__ __align__(16) f16 g_xi_f[MAXN * C_DIM];
__device__ __align__(16) f16 g_h_f [MAXN * C_DIM];
__device__ __align__(16) f16 g_a_f [MAXN * C_DIM];
__device__ __align__(16) f16 g_p_f [MAXN * C_DIM];

// per conv: BCAT[512,256] (W1T rows 0-255 | WxT rows 256-511) | W2T[256,256] | WaT[256,256]
// all K-major [n, k], K = 256, fp16 (round-to-nearest)
#define WSTRIDE (1024 * 256)
__device__ __align__(16) f16 g_w[4 * WSTRIDE];

// ---------------- helpers ----------------
__device__ __forceinline__ uint32_t smem_u32(const void* p) {
    uint32_t a;
    asm("{ .reg .u64 t; cvta.to.shared.u64 t, %1; cvt.u32.u64 %0, t; }" : "=r"(a) : "l"(p));
    return a;
}
__device__ __forceinline__ void cp16(uint32_t s, const void* g) {
    asm volatile("cp.async.cg.shared.global [%0], [%1], 16;" :: "r"(s), "l"(g));
}
__device__ __forceinline__ void cp_commit() { asm volatile("cp.async.commit_group;" ::: "memory"); }
template<int N> __device__ __forceinline__ void cp_wait() {
    asm volatile("cp.async.wait_group %0;" :: "n"(N) : "memory");
}
#define SW128(o) ((o) ^ (((o) >> 3) & 0x70))

__device__ __forceinline__ uint32_t pack_h2(float a, float b) {
    __half2 t = __halves2half2(__float2half_rn(a), __float2half_rn(b));
    return *reinterpret_cast<uint32_t*>(&t);
}

#define LDSM4(r0, r1, r2, r3, addr) \
    asm volatile("ldmatrix.sync.aligned.m8n8.x4.shared.b16 {%0,%1,%2,%3}, [%4];" \
                 : "=r"(r0), "=r"(r1), "=r"(r2), "=r"(r3) : "r"(addr))

#define MMA16816F(d, a, b0, b1) \
    asm volatile("mma.sync.aligned.m16n8k16.row.col.f32.f16.f16.f32 " \
                 "{%0,%1,%2,%3}, {%4,%5,%6,%7}, {%8,%9}, {%0,%1,%2,%3};" \
                 : "+f"((d)[0]), "+f"((d)[1]), "+f"((d)[2]), "+f"((d)[3]) \
                 : "r"((a)[0]), "r"((a)[1]), "r"((a)[2]), "r"((a)[3]), \
                   "r"(b0), "r"(b1))

// ---------------- warp-MMA GEMM (single-term fp16) ----------------
// out[M, *] = A[M,256] @ B^T; A,B fp16 (B K-major [n,256]).
// Block tile 128(M) x 128(N), 8 warps (2m x 4n), warp tile 64x32, K chunk 64.
// EPI 0: outH = f16(D + bias1)                            (P)
// EPI 1: outF += D                                        (new += agg@Wa)
// EPI 3: cols<256 -> outH = f16(relu(D+bias1)); cols>=256 -> outF = D + bias2
#define CHUNK_BYTES 32768       // A 16K | B 16K
#define GEMM_SMEM   (2 * CHUNK_BYTES)

__device__ __forceinline__ void gemm_load_chunk(
    uint32_t sbuf, int tid, int m0, int n0, int M, int c,
    const f16* Af, const f16* Bf)
{
    const int k0 = c * 64;
#pragma unroll
    for (int i = 0; i < 4; i++) {              // A: 128 rows x 128B
        int idx = tid + i * 256;
        int r = idx >> 3, u = idx & 7;
        int rg = min(m0 + r, M - 1);
        uint32_t so = SW128((uint32_t)(r * 128 + u * 16));
        cp16(sbuf + so, (const char*)(Af + (size_t)rg * C_DIM + k0) + u * 16);
    }
#pragma unroll
    for (int i = 0; i < 4; i++) {              // B: 128 n-rows x 128B
        int idx = tid + i * 256;
        int r = idx >> 3, u = idx & 7;
        uint32_t so = SW128((uint32_t)(r * 128 + u * 16));
        cp16(sbuf + 16384 + so, (const char*)(Bf + (size_t)(n0 + r) * C_DIM + k0) + u * 16);
    }
}

template<int EPI>
__global__ __launch_bounds__(256, 2)
void gemm_mma(const f16* __restrict__ Af, const f16* __restrict__ Bf,
              const float* __restrict__ bias1, const float* __restrict__ bias2,
              float* __restrict__ outF, f16* __restrict__ outH, int M)
{
    extern __shared__ char smem[];
    const uint32_t sb = smem_u32(smem);
    const int tid  = threadIdx.x;
    const int lane = tid & 31;
    const int wid  = tid >> 5;
    const int wm   = wid >> 2;
    const int wn   = wid & 3;
    const int m0   = blockIdx.x * 128;
    const int n0   = blockIdx.y * 128;

    const uint32_t aOff = (uint32_t)((wm * 64 + (lane & 15)) * 128 + ((lane >> 4) << 4));
    const uint32_t bOff = (uint32_t)((wn * 32 + (lane & 7) + ((lane >> 4) << 3)) * 128
                                     + (((lane >> 3) & 1) << 4));

    float D[4][4][4];
#pragma unroll
    for (int g = 0; g < 4; g++)
#pragma unroll
        for (int n = 0; n < 4; n++)
#pragma unroll
            for (int q = 0; q < 4; q++) D[g][n][q] = 0.f;

    gemm_load_chunk(sb, tid, m0, n0, M, 0, Af, Bf);
    cp_commit();

#pragma unroll
    for (int c = 0; c < 4; c++) {
        if (c + 1 < 4) {
            gemm_load_chunk(sb + (uint32_t)((c + 1) & 1) * CHUNK_BYTES,
                            tid, m0, n0, M, c + 1, Af, Bf);
            cp_commit();
            cp_wait<1>();
        } else {
            cp_wait<0>();
        }
        __syncthreads();

        const uint32_t base = sb + (uint32_t)(c & 1) * CHUNK_BYTES;
#pragma unroll
        for (int ks = 0; ks < 4; ks++) {
            const uint32_t kb = (uint32_t)(ks * 32);
            uint32_t af[4][4];
#pragma unroll
            for (int g = 0; g < 4; g++) {
                uint32_t sw = SW128(aOff + (uint32_t)(g * 2048) + kb);
                LDSM4(af[g][0], af[g][1], af[g][2], af[g][3], base + sw);
            }
            uint32_t bh[2][4];
#pragma unroll
            for (int p = 0; p < 2; p++) {
                uint32_t sw = SW128(bOff + (uint32_t)(p * 2048) + kb);
                LDSM4(bh[p][0], bh[p][1], bh[p][2], bh[p][3], base + 16384 + sw);
            }
#pragma unroll
            for (int g = 0; g < 4; g++) {
#pragma unroll
                for (int n = 0; n < 4; n++) {
                    const int p = n >> 1, rb = (n & 1) * 2;
                    MMA16816F(D[g][n], af[g], bh[p][rb], bh[p][rb + 1]);
                }
            }
        }
        __syncthreads();
    }

    // ---- epilogue ----
#pragma unroll
    for (int g = 0; g < 4; g++) {
#pragma unroll
        for (int n = 0; n < 4; n++) {
            int r0  = m0 + wm * 64 + g * 16 + (lane >> 2);
            int col = n0 + wn * 32 + n * 8 + (lane & 3) * 2;
            if (EPI == 0) {
                float2 bv = *(const float2*)(bias1 + col);
                if (r0 < M)
                    *(uint32_t*)(outH + (size_t)r0 * C_DIM + col) =
                        pack_h2(D[g][n][0] + bv.x, D[g][n][1] + bv.y);
                if (r0 + 8 < M)
                    *(uint32_t*)(outH + (size_t)(r0 + 8) * C_DIM + col) =
                        pack_h2(D[g][n][2] + bv.x, D[g][n][3] + bv.y);
            } else if (EPI == 1) {
                if (r0 < M) {
                    float2* p = (float2*)(outF + (size_t)r0 * C_DIM + col);
                    float2 o = *p;
                    *p = make_float2(o.x + D[g][n][0], o.y + D[g][n][1]);
                }
                if (r0 + 8 < M) {
                    float2* p = (float2*)(outF + (size_t)(r0 + 8) * C_DIM + col);
                    float2 o = *p;
                    *p = make_float2(o.x + D[g][n][2], o.y + D[g][n][3]);
                }
            } else {  // EPI 3
                if (col < 256) {
                    float2 bv = *(const float2*)(bias1 + col);
                    if (r0 < M)
                        *(uint32_t*)(outH + (size_t)r0 * C_DIM + col) =
                            pack_h2(fmaxf(D[g][n][0] + bv.x, 0.f),
                                    fmaxf(D[g][n][1] + bv.y, 0.f));
                    if (r0 + 8 < M)
                        *(uint32_t*)(outH + (size_t)(r0 + 8) * C_DIM + col) =
                            pack_h2(fmaxf(D[g][n][2] + bv.x, 0.f),
                                    fmaxf(D[g][n][3] + bv.y, 0.f));
                } else {
                    int cf = col - 256;
                    float2 bv = *(const float2*)(bias2 + cf);
                    if (r0 < M)
                        *(float2*)(outF + (size_t)r0 * C_DIM + cf) =
                            make_float2(D[g][n][0] + bv.x, D[g][n][1] + bv.y);
                    if (r0 + 8 < M)
                        *(float2*)(outF + (size_t)(r0 + 8) * C_DIM + cf) =
                            make_float2(D[g][n][2] + bv.x, D[g][n][3] + bv.y);
                }
            }
        }
    }
}

// ---------------- aux kernels ----------------
__device__ __forceinline__ float warp_sum(float v) {
#pragma unroll
    for (int o = 16; o > 0; o >>= 1) v += __shfl_xor_sync(0xffffffffu, v, o);
    return v;
}

__global__ void f32_to_f16_kernel(const float* __restrict__ x,
                                  f16* __restrict__ out, int n4)
{
    int idx = blockIdx.x * blockDim.x + threadIdx.x;
    if (idx >= n4) return;
    float4 v = ((const float4*)x)[idx];
    *(uint2*)(out + (size_t)idx * 4) = make_uint2(pack_h2(v.x, v.y), pack_h2(v.z, v.w));
}

// W [256 rows(k), 256 cols(n)] row-major -> dst[n*256+k] fp16
__global__ void convert_w_kernel(const float* __restrict__ W, f16* __restrict__ out)
{
    int idx = blockIdx.x * blockDim.x + threadIdx.x;
    if (idx >= 65536) return;
    int n = idx >> 8, k = idx & 255;
    out[idx] = __float2half_rn(W[(size_t)k * 256 + n]);
}

__global__ void count_kernel(const int* __restrict__ dst, float* __restrict__ cnt, int nE)
{
    int i = blockIdx.x * blockDim.x + threadIdx.x;
    if (i < nE) atomicAdd(cnt + __ldg(dst + i), 1.0f);
}

// fp16 edge stage: msg = LN(x_src[s] - P[d]) * g + b, red into fp32 agg
__global__ void edge_msg_kernel(const f16* __restrict__ xsrc,
                                const f16* __restrict__ Pn,
                                const int* __restrict__ ei,
                                const float* __restrict__ gg,
                                const float* __restrict__ bb,
                                float* __restrict__ agg, int nE)
{
    int w = (blockIdx.x * blockDim.x + threadIdx.x) >> 5;
    int lane = threadIdx.x & 31;
    if (w >= nE) return;
    int s = __ldg(ei + w);
    int d = __ldg(ei + nE + w);
    int c0 = lane << 3;

    uint4 xv = *(const uint4*)(xsrc + (size_t)s * C_DIM + c0);
    uint4 pv = *(const uint4*)(Pn   + (size_t)d * C_DIM + c0);
    const __half2* xh = (const __half2*)&xv;
    const __half2* ph = (const __half2*)&pv;
    float r[8];
#pragma unroll
    for (int i = 0; i < 4; i++) {
        float2 xf = __half22float2(xh[i]);
        float2 pf = __half22float2(ph[i]);
        r[i * 2]     = xf.x - pf.x;
        r[i * 2 + 1] = xf.y - pf.y;
    }
    float s1 = 0.f;
#pragma unroll
    for (int i = 0; i < 8; i++) s1 += r[i];
    float mean = warp_sum(s1) * (1.f / 256.f);
    float s2 = 0.f;
#pragma unroll
    for (int i = 0; i < 8; i++) { float t = r[i] - mean; s2 += t * t; }
    float inv = rsqrtf(warp_sum(s2) * (1.f / 256.f) + EPS_LN);
    float4 g0 = *(const float4*)(gg + c0), g1 = *(const float4*)(gg + c0 + 4);
    float4 e0 = *(const float4*)(bb + c0), e1 = *(const float4*)(bb + c0 + 4);
    float m0v = (r[0] - mean) * inv * g0.x + e0.x;
    float m1v = (r[1] - mean) * inv * g0.y + e0.y;
    float m2v = (r[2] - mean) * inv * g0.z + e0.z;
    float m3v = (r[3] - mean) * inv * g0.w + e0.w;
    float m4v = (r[4] - mean) * inv * g1.x + e1.x;
    float m5v = (r[5] - mean) * inv * g1.y + e1.y;
    float m6v = (r[6] - mean) * inv * g1.z + e1.z;
    float m7v = (r[7] - mean) * inv * g1.w + e1.w;
    float* dstp = agg + (size_t)d * C_DIM + c0;
    asm volatile("red.global.add.v4.f32 [%0], {%1,%2,%3,%4};"
                 :: "l"(dstp), "f"(m0v), "f"(m1v), "f"(m2v), "f"(m3v) : "memory");
    asm volatile("red.global.add.v4.f32 [%0], {%1,%2,%3,%4};"
                 :: "l"(dstp + 4), "f"(m4v), "f"(m5v), "f"(m6v), "f"(m7v) : "memory");
}

// agg/max(cnt,1) -> fp16
__global__ void norm_agg_f16_kernel(const float* __restrict__ agg,
                                    const float* __restrict__ cnt,
                                    f16* __restrict__ out, int n)
{
    int idx = blockIdx.x * blockDim.x + threadIdx.x;
    if (idx >= n * 64) return;
    int row = idx >> 6;
    float inv = 1.f / fmaxf(__ldg(cnt + row), 1.f);
    float4 v = ((const float4*)agg)[idx];
    *(uint2*)(out + (size_t)idx * 4) =
        make_uint2(pack_h2(v.x * inv, v.y * inv), pack_h2(v.z * inv, v.w * inv));
}

// out = relu(LN(X)*g+b); fp32 out (nullable), fp16 out (nullable)
__global__ void node_ln_relu_kernel(const float* __restrict__ X,
                                    const float* __restrict__ gg, const float* __restrict__ bb,
                                    float* __restrict__ out, f16* __restrict__ outh, int M)
{
    int w = (blockIdx.x * blockDim.x + threadIdx.x) >> 5;
    int lane = threadIdx.x & 31;
    if (w >= M) return;
    int c0 = lane << 3;
    const float4* xp = (const float4*)(X + (size_t)w * C_DIM + c0);
    float4 a0 = xp[0], a1 = xp[1];
    float r[8] = {a0.x, a0.y, a0.z, a0.w, a1.x, a1.y, a1.z, a1.w};
    float s1 = 0.f;
#pragma unroll
    for (int i = 0; i < 8; i++) s1 += r[i];
    float mean = warp_sum(s1) * (1.f / 256.f);
    float s2 = 0.f;
#pragma unroll
    for (int i = 0; i < 8; i++) { float t = r[i] - mean; s2 += t * t; }
    float inv = rsqrtf(warp_sum(s2) * (1.f / 256.f) + EPS_LN);
    float4 g0 = *(const float4*)(gg + c0), g1 = *(const float4*)(gg + c0 + 4);
    float4 e0 = *(const float4*)(bb + c0), e1 = *(const float4*)(bb + c0 + 4);
    float o[8];
    o[0] = fmaxf((r[0] - mean) * inv * g0.x + e0.x, 0.f);
    o[1] = fmaxf((r[1] - mean) * inv * g0.y + e0.y, 0.f);
    o[2] = fmaxf((r[2] - mean) * inv * g0.z + e0.z, 0.f);
    o[3] = fmaxf((r[3] - mean) * inv * g0.w + e0.w, 0.f);
    o[4] = fmaxf((r[4] - mean) * inv * g1.x + e1.x, 0.f);
    o[5] = fmaxf((r[5] - mean) * inv * g1.y + e1.y, 0.f);
    o[6] = fmaxf((r[6] - mean) * inv * g1.z + e1.z, 0.f);
    o[7] = fmaxf((r[7] - mean) * inv * g1.w + e1.w, 0.f);
    if (out) {
        float4* op = (float4*)(out + (size_t)w * C_DIM + c0);
        op[0] = make_float4(o[0], o[1], o[2], o[3]);
        op[1] = make_float4(o[4], o[5], o[6], o[7]);
    }
    if (outh) {
        *(uint4*)(outh + (size_t)w * C_DIM + c0) =
            make_uint4(pack_h2(o[0], o[1]), pack_h2(o[2], o[3]),
                       pack_h2(o[4], o[5]), pack_h2(o[6], o[7]));
    }
}

// ---------------- host ----------------
extern "C" void kernel_launch(void* const* d_in, const int* in_sizes, int n_in,
                              void* d_out, int out_size)
{
    const float* x_user = (const float*)d_in[0];
    const float* x_item = (const float*)d_in[1];
    const float* pw1    = (const float*)d_in[2];
    const float* pb1    = (const float*)d_in[3];
    const float* pw2    = (const float*)d_in[4];
    const float* pb2    = (const float*)d_in[5];
    const float* msg_g  = (const float*)d_in[6];
    const float* msg_b  = (const float*)d_in[7];
    const float* lin_w  = (const float*)d_in[8];
    const float* lin_b  = (const float*)d_in[9];
    const float* node_g = (const float*)d_in[10];
    const float* node_b = (const float*)d_in[11];
    const int*   ei_ui  = (const int*)d_in[12];
    const int*   ei_iu  = (const int*)d_in[13];

    const int NUn = in_sizes[0] / C_DIM;
    const int NIn = in_sizes[1] / C_DIM;
    const int nE0 = in_sizes[12] / 2;
    const int nE1 = in_sizes[13] / 2;
    const int Lm = 2;

    float *aggb, *new_u, *new_i, *cnt_i, *cnt_u;
    f16 *xu_f, *xi_f, *h_f, *a_f, *p_f, *w_f;
    cudaGetSymbolAddress((void**)&aggb, g_agg);
    cudaGetSymbolAddress((void**)&new_u, g_new_u);
    cudaGetSymbolAddress((void**)&new_i, g_new_i);
    cudaGetSymbolAddress((void**)&cnt_i, g_cnt_i);
    cudaGetSymbolAddress((void**)&cnt_u, g_cnt_u);
    cudaGetSymbolAddress((void**)&xu_f, g_xu_f);
    cudaGetSymbolAddress((void**)&xi_f, g_xi_f);
    cudaGetSymbolAddress((void**)&h_f, g_h_f);
    cudaGetSymbolAddress((void**)&a_f, g_a_f);
    cudaGetSymbolAddress((void**)&p_f, g_p_f);
    cudaGetSymbolAddress((void**)&w_f, g_w);

    cudaFuncSetAttribute(gemm_mma<0>, cudaFuncAttributeMaxDynamicSharedMemorySize, GEMM_SMEM);
    cudaFuncSetAttribute(gemm_mma<1>, cudaFuncAttributeMaxDynamicSharedMemorySize, GEMM_SMEM);
    cudaFuncSetAttribute(gemm_mma<3>, cudaFuncAttributeMaxDynamicSharedMemorySize, GEMM_SMEM);

    // weights -> transposed fp16
    for (int t = 0; t < 4; t++) {
        size_t wo = (size_t)t * WSTRIDE;
        convert_w_kernel<<<256, 256>>>(pw1 + (size_t)t * 65536, w_f + wo);               // W1T
        convert_w_kernel<<<256, 256>>>(lin_w + (size_t)t * 131072, w_f + wo + 65536);    // WxT
        convert_w_kernel<<<256, 256>>>(pw2 + (size_t)t * 65536, w_f + wo + 131072);      // W2T
        convert_w_kernel<<<256, 256>>>(lin_w + (size_t)t * 131072 + 65536, w_f + wo + 196608); // WaT
    }
    f32_to_f16_kernel<<<(NUn * 64 + 255) / 256, 256>>>(x_user, xu_f, NUn * 64);
    f32_to_f16_kernel<<<(NIn * 64 + 255) / 256, 256>>>(x_item, xi_f, NIn * 64);

    // degree counts (edge arrays shared across layers)
    cudaMemsetAsync(cnt_i, 0, (size_t)NIn * sizeof(float));
    cudaMemsetAsync(cnt_u, 0, (size_t)NUn * sizeof(float));
    count_kernel<<<(nE0 + 255) / 256, 256>>>(ei_ui + nE0, cnt_i, nE0);
    count_kernel<<<(nE1 + 255) / 256, 256>>>(ei_iu + nE1, cnt_u, nE1);

    float* out_f = (float*)d_out;

    for (int l = 0; l < Lm; l++) {
        bool last = (l == Lm - 1);
        // ---- conv: dst = item, src = user (params [l,0]) ----
        {
            int t = l * 2 + 0;
            size_t wo = (size_t)t * WSTRIDE;
            dim3 g4((NIn + 127) / 128, 4), g2((NIn + 127) / 128, 2);
            gemm_mma<3><<<g4, 256, GEMM_SMEM>>>(xi_f, w_f + wo,
                pb1 + (size_t)t * C_DIM, lin_b + (size_t)t * C_DIM, new_i, h_f, NIn);
            gemm_mma<0><<<g2, 256, GEMM_SMEM>>>(h_f, w_f + wo + 131072,
                pb2 + (size_t)t * C_DIM, (float*)0, (float*)0, p_f, NIn);
            cudaMemsetAsync(aggb, 0, (size_t)NIn * C_DIM * sizeof(float));
            edge_msg_kernel<<<(nE0 * 32 + 255) / 256, 256>>>(xu_f, p_f, ei_ui,
                msg_g + (size_t)t * C_DIM, msg_b + (size_t)t * C_DIM, aggb, nE0);
            norm_agg_f16_kernel<<<(NIn * 64 + 255) / 256, 256>>>(aggb, cnt_i, a_f, NIn);
            gemm_mma<1><<<g2, 256, GEMM_SMEM>>>(a_f, w_f + wo + 196608,
                (float*)0, (float*)0, new_i, (f16*)0, NIn);
        }
        // ---- conv: dst = user, src = item (params [l,1]) ----
        {
            int t = l * 2 + 1;
            size_t wo = (size_t)t * WSTRIDE;
            dim3 g4((NUn + 127) / 128, 4), g2((NUn + 127) / 128, 2);
            gemm_mma<3><<<g4, 256, GEMM_SMEM>>>(xu_f, w_f + wo,
                pb1 + (size_t)t * C_DIM, lin_b + (size_t)t * C_DIM, new_u, h_f, NUn);
            gemm_mma<0><<<g2, 256, GEMM_SMEM>>>(h_f, w_f + wo + 131072,
                pb2 + (size_t)t * C_DIM, (float*)0, (float*)0, p_f, NUn);
            cudaMemsetAsync(aggb, 0, (size_t)NUn * C_DIM * sizeof(float));
            edge_msg_kernel<<<(nE1 * 32 + 255) / 256, 256>>>(xi_f, p_f, ei_iu,
                msg_g + (size_t)t * C_DIM, msg_b + (size_t)t * C_DIM, aggb, nE1);
            norm_agg_f16_kernel<<<(NUn * 64 + 255) / 256, 256>>>(aggb, cnt_u, a_f, NUn);
            gemm_mma<1><<<g2, 256, GEMM_SMEM>>>(a_f, w_f + wo + 196608,
                (float*)0, (float*)0, new_u, (f16*)0, NUn);
        }
        // ---- node LN + relu ----
        // NOTE: GEMM<3> of the user conv reads xu_f; both convs above complete
        // before we overwrite xu_f/xi_f here (stream order).
        node_ln_relu_kernel<<<(NUn * 32 + 255) / 256, 256>>>(new_u,
            node_g + (size_t)(l * 2 + 0) * C_DIM, node_b + (size_t)(l * 2 + 0) * C_DIM,
            last ? out_f : (float*)0, last ? (f16*)0 : xu_f, NUn);
        node_ln_relu_kernel<<<(NIn * 32 + 255) / 256, 256>>>(new_i,
            node_g + (size_t)(l * 2 + 1) * C_DIM, node_b + (size_t)(l * 2 + 1) * C_DIM,
            last ? (out_f + (size_t)NUn * C_DIM) : (float*)0, last ? (f16*)0 : xi_f, NIn);
    }
    (void)n_in; (void)out_size;
}